// round 4
// baseline (speedup 1.0000x reference)
#include <cuda_runtime.h>
#include <cuda_bf16.h>
#include <cstdint>

// SocialPooling: two chained mma.sync bf16 GEMMs, fused per-k16.
//   stage1: S_g[64x128] = M_g[64x64(0/1)] @ (H_hi + H_lo)   (fp32 accum)
//   stage2: out[64x64] += S_hi@W_hi + S_hi@W_lo + S_lo@W_hi
// CTA = 1 scene (M=64), 4 warps x 16 rows, 4 CTAs/SM target.

#define TPB 128

#define SM_HHI  0        // bf16 [64 row][128 h] swizzled = 16 KB
#define SM_HLO  16384    // 16 KB
#define SM_PX   32768    // float[64]
#define SM_PY   33024    // float[64]
#define SM_BM   33280    // u64 [16 cell][64 row] = 8 KB
#define SM_FLAG 41472    // u32[16]
#define SMEM_TOTAL 41536

// W fragments: [g][k16][n8][lane] uint4 = {Whi.b0, Whi.b1, Wlo.b0, Wlo.b1}
__device__ uint4 g_wfrags[16 * 8 * 8 * 32];

__device__ __forceinline__ uint32_t smem_u32(const void* p) {
    uint32_t a;
    asm("{ .reg .u64 t; cvta.to.shared.u64 t, %1; cvt.u32.u64 %0, t; }" : "=r"(a) : "l"(p));
    return a;
}
__device__ __forceinline__ uint32_t pack_bf16x2(float lo, float hi) {
    uint32_t r;
    asm("cvt.rn.satfinite.bf16x2.f32 %0, %1, %2;" : "=r"(r) : "f"(hi), "f"(lo));
    return r;
}
__device__ __forceinline__ float bflo(uint32_t p) { return __uint_as_float(p << 16); }
__device__ __forceinline__ float bfhi(uint32_t p) { return __uint_as_float(p & 0xFFFF0000u); }

__device__ __forceinline__ uint32_t mbits(unsigned long long v) {
    uint32_t r = (v & 1ull) ? 0x3F80u : 0u;
    if (v & 2ull) r |= 0x3F800000u;
    return r;
}

#define LDMX4T(r0, r1, r2, r3, addr) \
    asm volatile("ldmatrix.sync.aligned.m8n8.x4.trans.shared.b16 {%0,%1,%2,%3}, [%4];" \
                 : "=r"(r0), "=r"(r1), "=r"(r2), "=r"(r3) : "r"(addr))

#define MMA_BF16(d, a0, a1, a2, a3, b0, b1) \
    asm volatile("mma.sync.aligned.m16n8k16.row.col.f32.bf16.bf16.f32 " \
                 "{%0,%1,%2,%3}, {%4,%5,%6,%7}, {%8,%9}, {%0,%1,%2,%3};" \
                 : "+f"((d)[0]), "+f"((d)[1]), "+f"((d)[2]), "+f"((d)[3]) \
                 : "r"(a0), "r"(a1), "r"(a2), "r"(a3), "r"(b0), "r"(b1))

// ---------------- W prep: fragment-order hi/lo split ----------------
__global__ void sp_wprep(const float* __restrict__ weight) {
    int idx  = blockIdx.x * 256 + threadIdx.x;   // 32768
    int lane = idx & 31;
    int n8   = (idx >> 5) & 7;
    int k16  = (idx >> 8) & 7;
    int g    = idx >> 11;
    int n  = n8 * 8 + (lane >> 2);
    int k0 = g * 128 + k16 * 16 + (lane & 3) * 2;
    float w00 = weight[(size_t)(k0 + 0) * 64 + n];
    float w01 = weight[(size_t)(k0 + 1) * 64 + n];
    float w10 = weight[(size_t)(k0 + 8) * 64 + n];
    float w11 = weight[(size_t)(k0 + 9) * 64 + n];
    uint32_t h0 = pack_bf16x2(w00, w01);
    uint32_t h1 = pack_bf16x2(w10, w11);
    uint32_t l0 = pack_bf16x2(w00 - bflo(h0), w01 - bfhi(h0));
    uint32_t l1 = pack_bf16x2(w10 - bflo(h1), w11 - bfhi(h1));
    g_wfrags[idx] = make_uint4(h0, h1, l0, l1);
}

// ---------------- main kernel: one CTA = 1 scene (64 rows) ----------------
__global__ __launch_bounds__(TPB, 4)
void sp_main(const float* __restrict__ hidden,
             const float* __restrict__ pos,
             const float* __restrict__ bias,
             float* __restrict__ out)
{
    extern __shared__ char smem[];
    const int tid  = threadIdx.x;
    const int lane = tid & 31;
    const int wid  = tid >> 5;
    const int b    = blockIdx.x;

    float* px = (float*)(smem + SM_PX);
    float* py = (float*)(smem + SM_PY);
    unsigned long long* bm = (unsigned long long*)(smem + SM_BM);
    uint32_t* flag = (uint32_t*)(smem + SM_FLAG);

    if (tid < 64) {
        px[tid] = pos[((size_t)b * 64 + tid) * 2 + 0];
        py[tid] = pos[((size_t)b * 64 + tid) * 2 + 1];
    }
    #pragma unroll
    for (int it = 0; it < 8; it++) bm[tid + it * TPB] = 0ull;

    // H -> smem bf16 hi/lo, rows of 256B, 16B-chunk XOR swizzle
    #pragma unroll
    for (int it = 0; it < 8; it++) {
        int cid = tid + it * TPB;          // 0..1023 = row*16 + chunk
        int row = cid >> 4;
        int ch  = cid & 15;
        const float4* src = (const float4*)(hidden + ((size_t)b * 64 + row) * 128 + ch * 8);
        float4 v0 = src[0], v1 = src[1];
        uint32_t h0 = pack_bf16x2(v0.x, v0.y);
        uint32_t h1 = pack_bf16x2(v0.z, v0.w);
        uint32_t h2 = pack_bf16x2(v1.x, v1.y);
        uint32_t h3 = pack_bf16x2(v1.z, v1.w);
        uint32_t l0 = pack_bf16x2(v0.x - bflo(h0), v0.y - bfhi(h0));
        uint32_t l1 = pack_bf16x2(v0.z - bflo(h1), v0.w - bfhi(h1));
        uint32_t l2 = pack_bf16x2(v1.x - bflo(h2), v1.y - bfhi(h2));
        uint32_t l3 = pack_bf16x2(v1.z - bflo(h3), v1.w - bfhi(h3));
        uint32_t off = (uint32_t)(row * 256 + ((ch ^ (row & 7)) << 4));
        *(uint4*)(smem + SM_HHI + off) = make_uint4(h0, h1, h2, h3);
        *(uint4*)(smem + SM_HLO + off) = make_uint4(l0, l1, l2, l3);
    }
    __syncthreads();

    // neighbor bitmasks per (cell, row) — exact reference cell math
    if (tid < 64) {
        const int i = tid;
        const float xi = px[i], yi = py[i];
        for (int j = 0; j < 64; j++) {
            float dx = px[j] - xi, dy = py[j] - yi;
            if (j != i && fabsf(dx) <= 2.0f && fabsf(dy) <= 2.0f) {
                int gx = min(3, max(0, (int)floorf(dx + 2.0f)));
                int gy = min(3, max(0, (int)floorf(dy + 2.0f)));
                bm[(gy * 4 + gx) * 64 + i] |= (1ull << j);
            }
        }
    }
    __syncthreads();
    if (tid < 16) {
        unsigned long long o = 0;
        #pragma unroll 8
        for (int i = 0; i < 64; i++) o |= bm[tid * 64 + i];
        flag[tid] = (o != 0ull) ? 1u : 0u;
    }
    __syncthreads();

    // ---- GEMM: warp = 16-row strip, full n=64 ----
    const int i0 = wid * 16;
    const int qr = lane >> 2;          // l/4
    const int qc = (lane & 3) * 2;     // (l%4)*2

    float oacc[8][4];
    #pragma unroll
    for (int nb = 0; nb < 8; nb++) {
        float b0 = bias[nb * 8 + qc];
        float b1 = bias[nb * 8 + qc + 1];
        oacc[nb][0] = b0; oacc[nb][1] = b1; oacc[nb][2] = b0; oacc[nb][3] = b1;
    }

    const uint32_t sbu = smem_u32(smem);
    const uint32_t hrow = (uint32_t)(((lane >> 3) & 1) * 8 + (lane & 7));
    const uint32_t hrow_off = hrow * 256;
    const uint32_t cb = (uint32_t)(lane >> 4);
    const uint32_t l7 = (uint32_t)(lane & 7);

    for (int g = 0; g < 16; g++) {
        if (flag[g] == 0u) continue;

        const unsigned long long m0 = bm[g * 64 + i0 + qr];
        const unsigned long long m1 = bm[g * 64 + i0 + 8 + qr];

        // A-fragments for all 4 t-steps (mask bits, exact in bf16)
        uint32_t A[4][4];
        #pragma unroll
        for (int t = 0; t < 4; t++) {
            const int sh = t * 16 + qc;
            A[t][0] = mbits(m0 >> sh);
            A[t][1] = mbits(m1 >> sh);
            A[t][2] = mbits(m0 >> (sh + 8));
            A[t][3] = mbits(m1 >> (sh + 8));
        }

        // fused per-k16: stage1 -> convert -> stage2
        #pragma unroll
        for (int hc = 0; hc < 8; hc++) {
            float s0[4] = {0.f, 0.f, 0.f, 0.f};
            float s1[4] = {0.f, 0.f, 0.f, 0.f};
            const uint32_t ch  = (uint32_t)(hc * 2) + cb;
            #pragma unroll
            for (int t = 0; t < 4; t++) {
                const uint32_t off = hrow_off + (uint32_t)t * 4096 + ((ch ^ l7) << 4);
                uint32_t bh0, bh1, bh2, bh3, bl0, bl1, bl2, bl3;
                LDMX4T(bh0, bh1, bh2, bh3, sbu + SM_HHI + off);
                LDMX4T(bl0, bl1, bl2, bl3, sbu + SM_HLO + off);
                MMA_BF16(s0, A[t][0], A[t][1], A[t][2], A[t][3], bh0, bh1);
                MMA_BF16(s1, A[t][0], A[t][1], A[t][2], A[t][3], bh2, bh3);
                MMA_BF16(s0, A[t][0], A[t][1], A[t][2], A[t][3], bl0, bl1);
                MMA_BF16(s1, A[t][0], A[t][1], A[t][2], A[t][3], bl2, bl3);
            }

            uint32_t ah0 = pack_bf16x2(s0[0], s0[1]);
            uint32_t ah1 = pack_bf16x2(s0[2], s0[3]);
            uint32_t ah2 = pack_bf16x2(s1[0], s1[1]);
            uint32_t ah3 = pack_bf16x2(s1[2], s1[3]);
            uint32_t al0 = pack_bf16x2(s0[0] - bflo(ah0), s0[1] - bfhi(ah0));
            uint32_t al1 = pack_bf16x2(s0[2] - bflo(ah1), s0[3] - bfhi(ah1));
            uint32_t al2 = pack_bf16x2(s1[0] - bflo(ah2), s1[1] - bfhi(ah2));
            uint32_t al3 = pack_bf16x2(s1[2] - bflo(ah3), s1[3] - bfhi(ah3));

            const uint4* wp = g_wfrags + (size_t)((g * 8 + hc) * 8) * 32 + lane;
            #pragma unroll
            for (int nb = 0; nb < 8; nb++) {
                uint4 w = wp[nb * 32];
                MMA_BF16(oacc[nb], ah0, ah1, ah2, ah3, w.x, w.y);  // Shi*Whi
                MMA_BF16(oacc[nb], ah0, ah1, ah2, ah3, w.z, w.w);  // Shi*Wlo
                MMA_BF16(oacc[nb], al0, al1, al2, al3, w.x, w.y);  // Slo*Whi
            }
        }
    }

    // ---- epilogue ----
    float* orow  = out + ((size_t)b * 64 + i0 + qr) * 64 + qc;
    float* orow8 = orow + 8 * 64;
    #pragma unroll
    for (int nb = 0; nb < 8; nb++) {
        *(float2*)(orow  + nb * 8) = make_float2(oacc[nb][0], oacc[nb][1]);
        *(float2*)(orow8 + nb * 8) = make_float2(oacc[nb][2], oacc[nb][3]);
    }
}

extern "C" void kernel_launch(void* const* d_in, const int* in_sizes, int n_in,
                              void* d_out, int out_size)
{
    const float* hidden = (const float*)d_in[0];
    const float* pos    = (const float*)d_in[1];
    const float* weight = (const float*)d_in[2];
    const float* bias   = (const float*)d_in[3];
    float* out = (float*)d_out;

    const int total = in_sizes[0] / 128;     // 16384 rows
    const int grid  = total / 64;            // 256 CTAs (1 scene each)

    sp_wprep<<<128, 256>>>(weight);

    cudaFuncSetAttribute(sp_main, cudaFuncAttributeMaxDynamicSharedMemorySize, SMEM_TOTAL);
    sp_main<<<grid, TPB, SMEM_TOTAL>>>(hidden, pos, bias, out);
}